// round 7
// baseline (speedup 1.0000x reference)
#include <cuda_runtime.h>
#include <cuda_fp16.h>
#include <cstdint>
#include <math.h>

#define DIN   1024
#define DIMM  1024
#define NH    16
#define HD    64
#define SEQ   2048
#define BATCHN 2
#define MTOT  (BATCHN*SEQ)   // 4096
#define KD    1024

// ---------------------------------------------------------------------------
// Scratch (allocation-free rule: __device__ globals)
// ---------------------------------------------------------------------------
__device__ __align__(16) __half g_x16[MTOT*DIMM];
__device__ __align__(16) __half g_q16[MTOT*DIMM];
__device__ __align__(16) __half g_k16[MTOT*DIMM];
__device__ __align__(16) __half g_v16[MTOT*DIMM];
__device__ __align__(16) __half g_c16[MTOT*DIMM];
__device__ __align__(16) __half g_wq16[DIMM*DIMM];
__device__ __align__(16) __half g_wk16[DIMM*DIMM];
__device__ __align__(16) __half g_wv16[DIMM*DIMM];
__device__ __align__(16) __half g_wo16[DIMM*DIMM];

__device__ __forceinline__ uint32_t smem_to_u32(const void* smem_ptr) {
    uint32_t addr;
    asm("{ .reg .u64 tmp; cvta.to.shared.u64 tmp, %1; cvt.u32.u64 %0, tmp; }"
        : "=r"(addr) : "l"(smem_ptr));
    return addr;
}

__device__ __forceinline__ float fast_exp2(float x) {
    float y;
    asm("ex2.approx.ftz.f32 %0, %1;" : "=f"(y) : "f"(x));
    return y;
}

__device__ __forceinline__ void ldsm_x4(uint32_t& r0, uint32_t& r1,
                                        uint32_t& r2, uint32_t& r3, uint32_t addr) {
    asm volatile("ldmatrix.sync.aligned.m8n8.x4.shared.b16 {%0,%1,%2,%3}, [%4];"
        : "=r"(r0), "=r"(r1), "=r"(r2), "=r"(r3) : "r"(addr));
}

__device__ __forceinline__ void ldsm_x4_t(uint32_t& r0, uint32_t& r1,
                                          uint32_t& r2, uint32_t& r3, uint32_t addr) {
    asm volatile("ldmatrix.sync.aligned.m8n8.x4.trans.shared.b16 {%0,%1,%2,%3}, [%4];"
        : "=r"(r0), "=r"(r1), "=r"(r2), "=r"(r3) : "r"(addr));
}

__device__ __forceinline__ void mma16816h(float* c, uint32_t a0, uint32_t a1,
                                          uint32_t a2, uint32_t a3,
                                          uint32_t b0, uint32_t b1) {
    asm volatile(
        "mma.sync.aligned.m16n8k16.row.col.f32.f16.f16.f32 "
        "{%0,%1,%2,%3}, {%4,%5,%6,%7}, {%8,%9}, {%0,%1,%2,%3};"
        : "+f"(c[0]), "+f"(c[1]), "+f"(c[2]), "+f"(c[3])
        : "r"(a0), "r"(a1), "r"(a2), "r"(a3), "r"(b0), "r"(b1));
}

#define CP_ASYNC16(dst, src) \
    asm volatile("cp.async.cg.shared.global [%0], [%1], 16;" :: "r"(dst), "l"(src) : "memory")
#define CP_COMMIT() asm volatile("cp.async.commit_group;" ::: "memory")
#define CP_WAIT0()  asm volatile("cp.async.wait_group 0;" ::: "memory")

// ---------------------------------------------------------------------------
// fp32 -> fp16 converts
// ---------------------------------------------------------------------------
__global__ void __launch_bounds__(256) f2h(const float* __restrict__ src,
                                           __half* __restrict__ dst, float scale)
{
    int idx = (blockIdx.x * 256 + threadIdx.x) * 4;
    float4 v = *(const float4*)&src[idx];
    *(__half2*)&dst[idx]     = __floats2half2_rn(v.x * scale, v.y * scale);
    *(__half2*)&dst[idx + 2] = __floats2half2_rn(v.z * scale, v.w * scale);
}

__global__ void __launch_bounds__(256) wcvt(const float* __restrict__ wq,
                                            const float* __restrict__ wk,
                                            const float* __restrict__ wv,
                                            const float* __restrict__ wo)
{
    const float SC = 0.18033688011112042f;   // 0.125 * log2(e)
    int mat = blockIdx.x >> 10;
    int idx = ((blockIdx.x & 1023) * 256 + threadIdx.x) * 4;
    const float* src; __half* dst; float s = 1.0f;
    switch (mat) {
        case 0: src = wq; dst = g_wq16; s = SC; break;
        case 1: src = wk; dst = g_wk16; break;
        case 2: src = wv; dst = g_wv16; break;
        default: src = wo; dst = g_wo16; break;
    }
    float4 v = *(const float4*)&src[idx];
    *(__half2*)&dst[idx]     = __floats2half2_rn(v.x * s, v.y * s);
    *(__half2*)&dst[idx + 2] = __floats2half2_rn(v.z * s, v.w * s);
}

// ---------------------------------------------------------------------------
// fp16 HMMA GEMM: 128x256 CTA tile, 64x64 warp tile (8 warps), BK=32,
// 3-stage cp.async. (unchanged from R6)
// ---------------------------------------------------------------------------
#define GS       3
#define BK       32
#define GKIT     (KD / BK)
#define STRIDE   40
#define A_HALVES (128 * STRIDE)
#define B_HALVES (256 * STRIDE)
#define STAGE_HALVES (A_HALVES + B_HALVES)
#define GEMM_SMEM (GS * STAGE_HALVES * 2)

__device__ __forceinline__ void gemm_fill_stage(
    uint32_t sm_base, int stage, int iter, int tid, int m0, int n0,
    const __half* __restrict__ Ag, const __half* __restrict__ Bg)
{
    const int k0 = iter * BK;
    const uint32_t stage_base = sm_base + stage * (STAGE_HALVES * 2);
    #pragma unroll
    for (int t = 0; t < 6; t++) {
        int c = tid + t * 256;
        if (c < 512) {
            int row = c >> 2, kc = (c & 3) * 8;
            CP_ASYNC16(stage_base + (row * STRIDE + kc) * 2,
                       &Ag[(size_t)(m0 + row) * KD + k0 + kc]);
        } else {
            int cb = c - 512;
            int row = cb >> 2, kc = (cb & 3) * 8;
            CP_ASYNC16(stage_base + A_HALVES * 2 + (row * STRIDE + kc) * 2,
                       &Bg[(size_t)(n0 + row) * KD + k0 + kc]);
        }
    }
    CP_COMMIT();
}

template<bool F32OUT>
__global__ void __launch_bounds__(256, 1) gemm_big(
    const __half* __restrict__ Ag,
    const __half* __restrict__ B0, const __half* __restrict__ B1,
    const __half* __restrict__ B2,
    void* __restrict__ C0, void* __restrict__ C1, void* __restrict__ C2,
    int tilesPerMat)
{
    extern __shared__ char smem[];
    const uint32_t sm_base = smem_to_u32(smem);
    const int tid  = threadIdx.x;
    const int wid  = tid >> 5;
    const int lane = tid & 31;
    const int m0  = blockIdx.y * 128;
    const int sel = blockIdx.x / tilesPerMat;
    const int n0  = (blockIdx.x % tilesPerMat) * 256;

    const __half* Bg = (sel == 0) ? B0 : (sel == 1) ? B1 : B2;
    void* Cv = (sel == 0) ? C0 : (sel == 1) ? C1 : C2;

    const int wm = (wid >> 2) * 64;
    const int wn = (wid & 3) * 64;

    const int q = lane >> 3;
    const int r = lane & 7;

    float acc[4][8][4];
    #pragma unroll
    for (int mi = 0; mi < 4; mi++)
        #pragma unroll
        for (int nf = 0; nf < 8; nf++)
            #pragma unroll
            for (int e = 0; e < 4; e++) acc[mi][nf][e] = 0.0f;

    #pragma unroll
    for (int s = 0; s < GS - 1; s++)
        gemm_fill_stage(sm_base, s, s, tid, m0, n0, Ag, Bg);

    for (int i = 0; i < GKIT; i++) {
        asm volatile("cp.async.wait_group %0;" :: "n"(GS - 2) : "memory");
        __syncthreads();

        const int j = i + GS - 1;
        if (j < GKIT)
            gemm_fill_stage(sm_base, j % GS, j, tid, m0, n0, Ag, Bg);

        const uint32_t abase = sm_base + (i % GS) * (STAGE_HALVES * 2);
        const uint32_t bbase = abase + A_HALVES * 2;

        #pragma unroll
        for (int ks = 0; ks < 2; ks++) {
            const int kh = ks * 16;
            uint32_t af[4][4];
            #pragma unroll
            for (int mi = 0; mi < 4; mi++) {
                int arow = wm + mi * 16 + (lane & 15);
                int acol = kh + (lane >> 4) * 8;
                ldsm_x4(af[mi][0], af[mi][1], af[mi][2], af[mi][3],
                        abase + (arow * STRIDE + acol) * 2);
            }
            uint32_t bf[8][2];
            #pragma unroll
            for (int p = 0; p < 4; p++) {
                int brow = wn + p * 16 + (q >> 1) * 8 + r;
                int bcol = kh + (q & 1) * 8;
                uint32_t b0, b1, b2, b3;
                ldsm_x4(b0, b1, b2, b3, bbase + (brow * STRIDE + bcol) * 2);
                bf[p * 2 + 0][0] = b0; bf[p * 2 + 0][1] = b1;
                bf[p * 2 + 1][0] = b2; bf[p * 2 + 1][1] = b3;
            }
            #pragma unroll
            for (int mi = 0; mi < 4; mi++)
                #pragma unroll
                for (int nf = 0; nf < 8; nf++)
                    mma16816h(acc[mi][nf], af[mi][0], af[mi][1], af[mi][2], af[mi][3],
                              bf[nf][0], bf[nf][1]);
        }
        __syncthreads();
    }

    const int gp = lane >> 2;
    const int t4 = lane & 3;
    #pragma unroll
    for (int mi = 0; mi < 4; mi++) {
        int row0 = m0 + wm + mi * 16 + gp;
        #pragma unroll
        for (int nf = 0; nf < 8; nf++) {
            int col = n0 + wn + nf * 8 + t4 * 2;
            if (F32OUT) {
                float* C = (float*)Cv;
                *(float2*)&C[(size_t)row0 * 1024 + col] =
                    make_float2(acc[mi][nf][0], acc[mi][nf][1]);
                *(float2*)&C[(size_t)(row0 + 8) * 1024 + col] =
                    make_float2(acc[mi][nf][2], acc[mi][nf][3]);
            } else {
                __half* C = (__half*)Cv;
                *(__half2*)&C[(size_t)row0 * 1024 + col] =
                    __floats2half2_rn(acc[mi][nf][0], acc[mi][nf][1]);
                *(__half2*)&C[(size_t)(row0 + 8) * 1024 + col] =
                    __floats2half2_rn(acc[mi][nf][2], acc[mi][nf][3]);
            }
        }
    }
}

// ---------------------------------------------------------------------------
// Tensor-core flash attention v2: BQ=128 q-rows per CTA, 4 warps,
// 32 q-rows per warp (2 m-frags share every K/V fragment).
// KV tiles of 64, double buffered via cp.async.
// ---------------------------------------------------------------------------
#define ASTR   72
#define AQ_B   (128 * ASTR * 2)          // 18432 Q tile
#define AP_B   (128 * ASTR * 2)          // 18432 P tile
#define AKV_B  (64 * ASTR * 2)           // 9216 per K or V buffer
#define AQOFF  0
#define APOFF  (AQ_B)
#define AKOFF  (AQ_B + AP_B)
#define AVOFF  (AKOFF + 2 * AKV_B)
#define ATTN_SMEM (AQ_B + AP_B + 4 * AKV_B)   // 73728
#define ABN   (-1e30f)

__device__ __forceinline__ void attn_prefetch(uint32_t smK, uint32_t smV,
                                              const __half* Kg, const __half* Vg,
                                              int tid)
{
    #pragma unroll
    for (int c = tid; c < 512; c += 128) {
        int row = c >> 3;
        int ch  = c & 7;
        uint32_t off = row * (ASTR * 2) + ch * 16;
        CP_ASYNC16(smK + off, Kg + (size_t)row * DIMM + ch * 8);
        CP_ASYNC16(smV + off, Vg + (size_t)row * DIMM + ch * 8);
    }
}

__global__ void __launch_bounds__(128, 1) attn_mma()
{
    extern __shared__ char smem[];
    const uint32_t sm = smem_to_u32(smem);
    const int tid  = threadIdx.x;
    const int w    = tid >> 5;
    const int lane = tid & 31;
    const int gp   = lane >> 2;
    const int t4   = lane & 3;
    const int qt = gridDim.x - 1 - blockIdx.x;   // big q-tiles first
    const int h  = blockIdx.y;
    const int b  = blockIdx.z;

    const int wm = w * 32;                       // warp q-row base (local)

    const __half* Qg = g_q16 + (size_t)(b * SEQ + qt * 128) * DIMM + h * HD;
    const __half* Kg = g_k16 + (size_t)(b * SEQ) * DIMM + h * HD;
    const __half* Vg = g_v16 + (size_t)(b * SEQ) * DIMM + h * HD;

    // Q tile: 128 rows x 8 chunks
    #pragma unroll
    for (int c = tid; c < 1024; c += 128) {
        int row = c >> 3, ch = c & 7;
        CP_ASYNC16(sm + AQOFF + row * (ASTR * 2) + ch * 16,
                   Qg + (size_t)row * DIMM + ch * 8);
    }
    CP_COMMIT();
    attn_prefetch(sm + AKOFF, sm + AVOFF, Kg, Vg, tid);
    CP_COMMIT();
    CP_WAIT0();
    __syncthreads();

    // Q fragments: 4 k-steps x 2 m-frags
    uint32_t aQ[4][2][4];
    #pragma unroll
    for (int ks = 0; ks < 4; ks++)
        #pragma unroll
        for (int mi = 0; mi < 2; mi++)
            ldsm_x4(aQ[ks][mi][0], aQ[ks][mi][1], aQ[ks][mi][2], aQ[ks][mi][3],
                    sm + AQOFF + ((wm + mi * 16 + (lane & 15)) * ASTR
                                  + ks * 16 + (lane >> 4) * 8) * 2);

    float oacc[2][8][4];
    #pragma unroll
    for (int mi = 0; mi < 2; mi++)
        #pragma unroll
        for (int nf = 0; nf < 8; nf++)
            #pragma unroll
            for (int e = 0; e < 4; e++) oacc[mi][nf][e] = 0.0f;
    float mrow[4] = {ABN, ABN, ABN, ABN};      // [mi*2 + half]
    float lrow[4] = {0.0f, 0.0f, 0.0f, 0.0f};

    const int ntiles = 2 * qt + 2;

    for (int t = 0; t < ntiles; t++) {
        const uint32_t bufK = sm + AKOFF + (t & 1) * AKV_B;
        const uint32_t bufV = sm + AVOFF + (t & 1) * AKV_B;

        if (t > 0) { CP_WAIT0(); __syncthreads(); }
        if (t + 1 < ntiles) {
            attn_prefetch(sm + AKOFF + ((t + 1) & 1) * AKV_B,
                          sm + AVOFF + ((t + 1) & 1) * AKV_B,
                          Kg + (size_t)(t + 1) * 64 * DIMM,
                          Vg + (size_t)(t + 1) * 64 * DIMM, tid);
            CP_COMMIT();
        }

        // ---- S = Q @ K^T
        float sacc[2][8][4];
        #pragma unroll
        for (int mi = 0; mi < 2; mi++)
            #pragma unroll
            for (int nf = 0; nf < 8; nf++)
                #pragma unroll
                for (int e = 0; e < 4; e++) sacc[mi][nf][e] = 0.0f;

        #pragma unroll
        for (int ks = 0; ks < 4; ks++) {
            #pragma unroll
            for (int p = 0; p < 4; p++) {
                uint32_t b0, b1, b2, b3;
                int brow = p * 16 + (lane >> 4) * 8 + (lane & 7);
                int bcol = ks * 16 + ((lane >> 3) & 1) * 8;
                ldsm_x4(b0, b1, b2, b3, bufK + (brow * ASTR + bcol) * 2);
                #pragma unroll
                for (int mi = 0; mi < 2; mi++) {
                    mma16816h(sacc[mi][2 * p],     aQ[ks][mi][0], aQ[ks][mi][1],
                              aQ[ks][mi][2], aQ[ks][mi][3], b0, b1);
                    mma16816h(sacc[mi][2 * p + 1], aQ[ks][mi][0], aQ[ks][mi][1],
                              aQ[ks][mi][2], aQ[ks][mi][3], b2, b3);
                }
            }
        }

        // ---- causal mask (last two kv tiles intersect the diagonal)
        if (t >= 2 * qt) {
            const int krel = (t - 2 * qt) * 64;   // kv offset rel. to q-tile base
            #pragma unroll
            for (int mi = 0; mi < 2; mi++) {
                const int q0 = wm + mi * 16 + gp;
                const int q1 = q0 + 8;
                #pragma unroll
                for (int nf = 0; nf < 8; nf++) {
                    int c = krel + nf * 8 + t4 * 2;
                    if (c     > q0) sacc[mi][nf][0] = ABN;
                    if (c + 1 > q0) sacc[mi][nf][1] = ABN;
                    if (c     > q1) sacc[mi][nf][2] = ABN;
                    if (c + 1 > q1) sacc[mi][nf][3] = ABN;
                }
            }
        }

        // ---- online softmax (4 row-groups per thread)
        #pragma unroll
        for (int mi = 0; mi < 2; mi++) {
            float mx0 = ABN, mx1 = ABN;
            #pragma unroll
            for (int nf = 0; nf < 8; nf++) {
                mx0 = fmaxf(mx0, fmaxf(sacc[mi][nf][0], sacc[mi][nf][1]));
                mx1 = fmaxf(mx1, fmaxf(sacc[mi][nf][2], sacc[mi][nf][3]));
            }
            mx0 = fmaxf(mx0, __shfl_xor_sync(0xFFFFFFFF, mx0, 1));
            mx0 = fmaxf(mx0, __shfl_xor_sync(0xFFFFFFFF, mx0, 2));
            mx1 = fmaxf(mx1, __shfl_xor_sync(0xFFFFFFFF, mx1, 1));
            mx1 = fmaxf(mx1, __shfl_xor_sync(0xFFFFFFFF, mx1, 2));

            const float mn0 = fmaxf(mrow[mi * 2],     mx0);
            const float mn1 = fmaxf(mrow[mi * 2 + 1], mx1);
            const float cr0 = fast_exp2(mrow[mi * 2]     - mn0);
            const float cr1 = fast_exp2(mrow[mi * 2 + 1] - mn1);
            lrow[mi * 2]     *= cr0;
            lrow[mi * 2 + 1] *= cr1;
            mrow[mi * 2]     = mn0;
            mrow[mi * 2 + 1] = mn1;

            char* prow0 = smem + APOFF + ((wm + mi * 16 + gp) * ASTR + t4 * 2) * 2;
            char* prow1 = prow0 + 8 * ASTR * 2;
            float l0 = 0.0f, l1 = 0.0f;
            #pragma unroll
            for (int nf = 0; nf < 8; nf++) {
                float p00 = fast_exp2(sacc[mi][nf][0] - mn0);
                float p01 = fast_exp2(sacc[mi][nf][1] - mn0);
                float p10 = fast_exp2(sacc[mi][nf][2] - mn1);
                float p11 = fast_exp2(sacc[mi][nf][3] - mn1);
                l0 += p00 + p01;
                l1 += p10 + p11;
                oacc[mi][nf][0] *= cr0; oacc[mi][nf][1] *= cr0;
                oacc[mi][nf][2] *= cr1; oacc[mi][nf][3] *= cr1;
                *(__half2*)(prow0 + nf * 16) = __floats2half2_rn(p00, p01);
                *(__half2*)(prow1 + nf * 16) = __floats2half2_rn(p10, p11);
            }
            lrow[mi * 2]     += l0;
            lrow[mi * 2 + 1] += l1;
        }
        __syncwarp();

        // ---- O += P @ V
        #pragma unroll
        for (int ks = 0; ks < 4; ks++) {
            uint32_t aP[2][4];
            #pragma unroll
            for (int mi = 0; mi < 2; mi++)
                ldsm_x4(aP[mi][0], aP[mi][1], aP[mi][2], aP[mi][3],
                        sm + APOFF + ((wm + mi * 16 + (lane & 15)) * ASTR
                                      + ks * 16 + (lane >> 4) * 8) * 2);
            #pragma unroll
            for (int p = 0; p < 4; p++) {
                uint32_t b0, b1, b2, b3;
                int vrow = ks * 16 + (lane & 15);
                int vcol = p * 16 + (lane >> 4) * 8;
                ldsm_x4_t(b0, b1, b2, b3, bufV + (vrow * ASTR + vcol) * 2);
                #pragma unroll
                for (int mi = 0; mi < 2; mi++) {
                    mma16816h(oacc[mi][2 * p],     aP[mi][0], aP[mi][1], aP[mi][2], aP[mi][3], b0, b1);
                    mma16816h(oacc[mi][2 * p + 1], aP[mi][0], aP[mi][1], aP[mi][2], aP[mi][3], b2, b3);
                }
            }
        }
    }

    // ---- epilogue
    #pragma unroll
    for (int i = 0; i < 4; i++) {
        lrow[i] += __shfl_xor_sync(0xFFFFFFFF, lrow[i], 1);
        lrow[i] += __shfl_xor_sync(0xFFFFFFFF, lrow[i], 2);
    }

    #pragma unroll
    for (int mi = 0; mi < 2; mi++) {
        const float inv0 = 1.0f / lrow[mi * 2];
        const float inv1 = 1.0f / lrow[mi * 2 + 1];
        const int qg = qt * 128 + wm + mi * 16 + gp;
        __half* orow = g_c16 + (size_t)(b * SEQ + qg) * DIMM + h * HD;
        #pragma unroll
        for (int nf = 0; nf < 8; nf++) {
            int col = nf * 8 + t4 * 2;
            *(__half2*)(orow + col) =
                __floats2half2_rn(oacc[mi][nf][0] * inv0, oacc[mi][nf][1] * inv0);
            *(__half2*)(orow + 8 * DIMM + col) =
                __floats2half2_rn(oacc[mi][nf][2] * inv1, oacc[mi][nf][3] * inv1);
        }
    }
}

// ---------------------------------------------------------------------------

extern "C" void kernel_launch(void* const* d_in, const int* in_sizes, int n_in,
                              void* d_out, int out_size)
{
    const float* x  = (const float*)d_in[0];
    const float* wq = (const float*)d_in[1];
    const float* wk = (const float*)d_in[2];
    const float* wv = (const float*)d_in[3];
    const float* wo = (const float*)d_in[4];
    float* out = (float*)d_out;

    __half *x16, *q16, *k16, *v16, *c16, *wq16, *wk16, *wv16, *wo16;
    cudaGetSymbolAddress((void**)&x16,  g_x16);
    cudaGetSymbolAddress((void**)&q16,  g_q16);
    cudaGetSymbolAddress((void**)&k16,  g_k16);
    cudaGetSymbolAddress((void**)&v16,  g_v16);
    cudaGetSymbolAddress((void**)&c16,  g_c16);
    cudaGetSymbolAddress((void**)&wq16, g_wq16);
    cudaGetSymbolAddress((void**)&wk16, g_wk16);
    cudaGetSymbolAddress((void**)&wv16, g_wv16);
    cudaGetSymbolAddress((void**)&wo16, g_wo16);

    cudaFuncSetAttribute(gemm_big<false>, cudaFuncAttributeMaxDynamicSharedMemorySize, GEMM_SMEM);
    cudaFuncSetAttribute(gemm_big<true>,  cudaFuncAttributeMaxDynamicSharedMemorySize, GEMM_SMEM);
    cudaFuncSetAttribute(attn_mma, cudaFuncAttributeMaxDynamicSharedMemorySize, ATTN_SMEM);

    f2h<<<(MTOT*DIMM)/(256*4), 256>>>(x, x16, 1.0f);
    wcvt<<<4 * (DIMM*DIMM)/(256*4), 256>>>(wq, wk, wv, wo);

    dim3 gq(12, MTOT / 128);
    gemm_big<false><<<gq, 256, GEMM_SMEM>>>(x16, wq16, wk16, wv16,
                                            q16, k16, v16, 4);

    dim3 agrid(SEQ / 128, NH, BATCHN);     // (16, 16, 2)
    attn_mma<<<agrid, 128, ATTN_SMEM>>>();

    dim3 go(4, MTOT / 128);
    gemm_big<true><<<go, 256, GEMM_SMEM>>>(c16, wo16, wo16, wo16,
                                           out, out, out, 4);
}